// round 1
// baseline (speedup 1.0000x reference)
#include <cuda_runtime.h>
#include <cstddef>

// Problem constants
#define BV 32
#define CV 80
#define GV 128
#define GGV (GV * GV)     // 16384
#define NV 32
#define NBLK 128
#define NTHR 256

// ---------------- scratch (device globals; no allocations) ----------------
__device__ int      g_cnt[BV];
__device__ int      g_cell[BV][NV];
__device__ int      g_flag[BV][NV];
__device__ float    g_regt[BV][NV][4];
__device__ unsigned g_clsm[BV][NV][3];
__device__ float    g_part[NBLK][7];

// ---------------- helpers ----------------
__device__ __forceinline__ float fsp(float x) {
    // softplus = max(x,0) + log(1 + exp(-|x|))  (matches jax.nn.softplus)
    return fmaxf(x, 0.0f) + __logf(1.0f + __expf(-fabsf(x)));
}

// ---------------- kernel 1: build dedup'ed targets ----------------
__global__ void k_build(const int* __restrict__ tcls, const float* __restrict__ tbox) {
    int b = threadIdx.x;
    if (b >= BV) return;
    int cnt = 0;
    for (int n = 0; n < NV; ++n) {
        const float* tb = tbox + (size_t)(b * NV + n) * 4;
        float x = tb[0], y = tb[1], w = tb[2], h = tb[3];
        float fx = x * (float)GV, fy = y * (float)GV;
        int gx = (int)floorf(fx);
        int gy = (int)floorf(fy);
        bool valid = (gx >= 0) && (gx < GV) && (gy >= 0) && (gy < GV);
        gx = min(max(gx, 0), GV - 1);
        gy = min(max(gy, 0), GV - 1);
        int cell = gy * GV + gx;
        int j = -1;
        for (int k = 0; k < cnt; ++k) {
            if (g_cell[b][k] == cell) { j = k; break; }
        }
        if (j < 0) {
            j = cnt++;
            g_cell[b][j] = cell;
            g_flag[b][j] = 0;
            g_clsm[b][j][0] = 0u; g_clsm[b][j][1] = 0u; g_clsm[b][j][2] = 0u;
        }
        float one = valid ? 1.0f : 0.0f;
        // .set semantics: last writer (in n order) wins, zeros if invalid
        g_regt[b][j][0] = (fx - (float)gx) * one;
        g_regt[b][j][1] = (fy - (float)gy) * one;
        g_regt[b][j][2] = sqrtf(w) * one;
        g_regt[b][j][3] = sqrtf(h) * one;
        if (valid) {
            g_flag[b][j] = 1;
            int c = tcls[b * NV + n];
            g_clsm[b][j][c >> 5] |= (1u << (c & 31));
        }
    }
    g_cnt[b] = cnt;
}

// ---------------- kernel 2: main reduction ----------------
__global__ void __launch_bounds__(NTHR) k_main(const float* __restrict__ cls,
                                               const float* __restrict__ reg,
                                               const float* __restrict__ obj) {
    float a0 = 0.f; // sum softplus(obj) over all cells
    float a1 = 0.f; // sum obj at masked cells
    float a2 = 0.f; // sum softplus(obj) at masked cells
    float a3 = 0.f; // masked cell count
    float a4 = 0.f; // sum softplus(cls) over masked cells x C
    float a5 = 0.f; // sum cls at target (b,c,cell) entries
    float a6 = 0.f; // sum squared reg diffs at masked cells

    const int tid = blockIdx.x * NTHR + threadIdx.x;
    const int nt  = NBLK * NTHR;

    // ---- dense softplus sum over obj_pred (float4 vectorized) ----
    {
        const float4* o4 = (const float4*)obj;
        const int n4 = BV * GGV / 4; // 131072
        float lin = 0.f;
        float prod = 1.f;
        int pc = 0;
        for (int i = tid; i < n4; i += nt) {
            float4 v = o4[i];
            lin += fmaxf(v.x, 0.f) + fmaxf(v.y, 0.f) + fmaxf(v.z, 0.f) + fmaxf(v.w, 0.f);
            prod *= (1.f + __expf(-fabsf(v.x)));
            prod *= (1.f + __expf(-fabsf(v.y)));
            prod *= (1.f + __expf(-fabsf(v.z)));
            prod *= (1.f + __expf(-fabsf(v.w)));
            if (++pc == 4) { lin += __logf(prod); prod = 1.f; pc = 0; } // flush every 16 elems
        }
        lin += __logf(prod);
        a0 = lin;
    }

    // ---- masked-cell gathers (<= 1024 cells total) ----
    for (int s = tid; s < BV * NV; s += nt) {
        int b = s >> 5;
        int j = s & 31;
        if (j < g_cnt[b] && g_flag[b][j]) {
            int cell = g_cell[b][j];
            float ov = obj[b * GGV + cell];
            a1 += ov;
            a2 += fsp(ov);
            a3 += 1.0f;
            const float* rt = g_regt[b][j];
#pragma unroll
            for (int c = 0; c < 4; ++c) {
                float d = reg[(b * 4 + c) * GGV + cell] - rt[c];
                a6 += d * d;
            }
            const float* base = cls + (size_t)b * CV * GGV + cell;
            unsigned m0 = g_clsm[b][j][0], m1 = g_clsm[b][j][1], m2 = g_clsm[b][j][2];
            float clin = 0.f, cprod = 1.f, ctgt = 0.f;
#pragma unroll
            for (int c = 0; c < CV; ++c) {
                float p = base[(size_t)c * GGV];
                clin += fmaxf(p, 0.f);
                cprod *= (1.f + __expf(-fabsf(p)));
                unsigned mw = (c < 32) ? m0 : ((c < 64) ? m1 : m2);
                if (mw & (1u << (c & 31))) ctgt += p;
                if ((c & 15) == 15) { clin += __logf(cprod); cprod = 1.f; }
            }
            a4 += clin;
            a5 += ctgt;
        }
    }

    // ---- hierarchical reduction: warp shuffle -> smem -> warp0 ----
    __shared__ float sm[NTHR / 32][7];
    float v[7] = {a0, a1, a2, a3, a4, a5, a6};
    int lane = threadIdx.x & 31;
    int wid  = threadIdx.x >> 5;
#pragma unroll
    for (int k = 0; k < 7; ++k) {
        float t = v[k];
#pragma unroll
        for (int o = 16; o; o >>= 1) t += __shfl_down_sync(0xffffffffu, t, o);
        if (lane == 0) sm[wid][k] = t;
    }
    __syncthreads();
    if (wid == 0) {
#pragma unroll
        for (int k = 0; k < 7; ++k) {
            float t = (lane < NTHR / 32) ? sm[lane][k] : 0.f;
#pragma unroll
            for (int o = 4; o; o >>= 1) t += __shfl_down_sync(0xffffffffu, t, o);
            if (lane == 0) g_part[blockIdx.x][k] = t;
        }
    }
}

// ---------------- kernel 3: deterministic finalize ----------------
__global__ void k_final(float* __restrict__ out) {
    __shared__ float red[NBLK];
    int t = threadIdx.x; // 128 threads
    float tot[7];
#pragma unroll
    for (int k = 0; k < 7; ++k) {
        red[t] = g_part[t][k];
        __syncthreads();
        for (int s = NBLK / 2; s > 0; s >>= 1) {
            if (t < s) red[t] += red[t + s];
            __syncthreads();
        }
        tot[k] = red[0];
        __syncthreads();
    }
    if (t == 0) {
        const double LN2 = 0.6931471805599453;
        double M      = (double)tot[3];
        double obj_l  = (double)tot[0] - (double)tot[1];
        double noobj  = 0.5 * ((double)tot[0] - (double)tot[2] + M * LN2);
        double coord  = 5.0 * (double)tot[6];
        double cls_l  = (double)CV * LN2 * ((double)(BV * GGV) - M)
                      + (double)tot[4] - (double)tot[5];
        double total  = obj_l + noobj + coord + cls_l;
        out[0] = (float)(total / (double)BV);
        out[1] = (float)(obj_l / (double)BV);
        out[2] = (float)(noobj / (double)BV);
        out[3] = (float)(coord / (double)BV);
        out[4] = (float)(cls_l / (double)BV);
    }
}

// ---------------- launch ----------------
extern "C" void kernel_launch(void* const* d_in, const int* in_sizes, int n_in,
                              void* d_out, int out_size) {
    // Identify inputs by element count (all distinct) to be robust to ordering.
    const float* cls = nullptr;   // 32*80*128*128 = 41943040
    const float* reg = nullptr;   // 32*4*128*128  = 2097152
    const float* obj = nullptr;   // 32*1*128*128  = 524288
    const int*   tcl = nullptr;   // 32*32         = 1024
    const float* tbx = nullptr;   // 32*32*4       = 4096
    for (int i = 0; i < n_in; ++i) {
        switch (in_sizes[i]) {
            case 41943040: cls = (const float*)d_in[i]; break;
            case 2097152:  reg = (const float*)d_in[i]; break;
            case 524288:   obj = (const float*)d_in[i]; break;
            case 1024:     tcl = (const int*)d_in[i];   break;
            case 4096:     tbx = (const float*)d_in[i]; break;
            default: break;
        }
    }
    float* out = (float*)d_out;

    k_build<<<1, 32>>>(tcl, tbx);
    k_main<<<NBLK, NTHR>>>(cls, reg, obj);
    k_final<<<1, NBLK>>>(out);
}

// round 2
// speedup vs baseline: 7.8478x; 7.8478x over previous
#include <cuda_runtime.h>
#include <cstddef>

// Problem constants
#define BV 32
#define CV 80
#define GV 128
#define GGV (GV * GV)     // 16384
#define NV 32
#define NBLK 128
#define NTHR 256

// ---------------- scratch (device globals; no allocations) ----------------
__device__ float g_part[NBLK][7];
__device__ int   g_sync = 0;   // reset to 0 by last block each run (graph-replay safe)

// ---------------- helpers ----------------
__device__ __forceinline__ float fsp(float x) {
    // softplus = max(x,0) + log(1 + exp(-|x|))  (matches jax.nn.softplus)
    return fmaxf(x, 0.0f) + __logf(1.0f + __expf(-fabsf(x)));
}

// ---------------- single fused kernel ----------------
__global__ void __launch_bounds__(NTHR) k_fused(const float* __restrict__ cls,
                                                const float* __restrict__ reg,
                                                const float* __restrict__ obj,
                                                const int*   __restrict__ tcl,
                                                const float* __restrict__ tbx,
                                                float* __restrict__ out) {
    float a0 = 0.f; // sum softplus(obj) over all cells
    float a1 = 0.f; // sum obj at masked cells
    float a2 = 0.f; // sum softplus(obj) at masked cells
    float a3 = 0.f; // masked unique-cell count
    float a4 = 0.f; // sum softplus(cls) over masked cells x C
    float a5 = 0.f; // sum cls at target (b,c,cell) entries
    float a6 = 0.f; // sum squared reg diffs at masked cells

    const int tid  = blockIdx.x * NTHR + threadIdx.x;
    const int lane = threadIdx.x & 31;
    const int wid  = threadIdx.x >> 5;
    const int gw   = tid >> 5;           // global warp id: 0..1023
    const unsigned FULL = 0xffffffffu;

    // ---- dense softplus sum over obj_pred (float4, 4 iters/thread) ----
    {
        const float4* o4 = (const float4*)obj;
        float lin = 0.f, prod = 1.f;
#pragma unroll
        for (int r = 0; r < 4; ++r) {
            float4 v = o4[tid + r * (NBLK * NTHR)];
            lin += fmaxf(v.x, 0.f) + fmaxf(v.y, 0.f) + fmaxf(v.z, 0.f) + fmaxf(v.w, 0.f);
            prod *= (1.f + __expf(-fabsf(v.x)));   // each factor in (1,2]; <=16 factors, fp32-safe
            prod *= (1.f + __expf(-fabsf(v.y)));
            prod *= (1.f + __expf(-fabsf(v.z)));
            prod *= (1.f + __expf(-fabsf(v.w)));
        }
        a0 = lin + __logf(prod);
    }

    // ---- warp-parallel target dedup: warp gw owns target (b, n) ----
    {
        const int b = gw >> 5;      // batch
        const int n = gw & 31;      // target index owned by this warp
        // lane L loads target L of batch b (coalesced: 512B contiguous)
        float4 tb = ((const float4*)tbx)[b * NV + lane];
        int    tc = tcl[b * NV + lane];
        float fx = tb.x * (float)GV, fy = tb.y * (float)GV;
        int gx = (int)floorf(fx);
        int gy = (int)floorf(fy);
        bool valid = (gx >= 0) && (gx < GV) && (gy >= 0) && (gy < GV);
        gx = min(max(gx, 0), GV - 1);
        gy = min(max(gy, 0), GV - 1);
        int cell = gy * GV + gx;
        float one = valid ? 1.f : 0.f;
        // reg_vals (zeroed when invalid — reference multiplies by `one`)
        float r0 = (fx - (float)gx) * one;
        float r1 = (fy - (float)gy) * one;
        float r2 = sqrtf(tb.z) * one;
        float r3 = sqrtf(tb.w) * one;

        int cell_n  = __shfl_sync(FULL, cell, n);
        int valid_n = __shfl_sync(FULL, (int)valid, n);
        unsigned matchAny = __ballot_sync(FULL, cell == cell_n);            // any validity (for .set last-wins)
        unsigned matchVal = __ballot_sync(FULL, valid && (cell == cell_n)); // valid writers (for mask/cls)

        // representative: target n is valid and is the FIRST valid lane with this cell
        bool rep = valid_n && ((matchVal & ((1u << n) - 1u)) == 0u);

        // last writer of reg_target at this cell (any validity; .set semantics)
        int k_last = 31 - __clz((int)matchAny);   // bit n always set
        float rv0 = __shfl_sync(FULL, r0, k_last);
        float rv1 = __shfl_sync(FULL, r1, k_last);
        float rv2 = __shfl_sync(FULL, r2, k_last);
        float rv3 = __shfl_sync(FULL, r3, k_last);

        // class bitmask for this cell (union over valid matching lanes)
        bool vm = valid && (cell == cell_n);
        unsigned m0 = __reduce_or_sync(FULL, (vm && tc < 32)             ? (1u << (tc & 31)) : 0u);
        unsigned m1 = __reduce_or_sync(FULL, (vm && tc >= 32 && tc < 64) ? (1u << (tc & 31)) : 0u);
        unsigned m2 = __reduce_or_sync(FULL, (vm && tc >= 64)            ? (1u << (tc & 31)) : 0u);

        if (rep) {
            // warp-parallel gather over the 80 classes (3 per lane)
            const float* base = cls + (size_t)b * CV * GGV + cell_n;
            float clin = 0.f, cprod = 1.f, ctgt = 0.f;
#pragma unroll
            for (int r = 0; r < 3; ++r) {
                int c = lane + r * 32;
                if (c < CV) {
                    float p = base[(size_t)c * GGV];
                    clin += fmaxf(p, 0.f);
                    cprod *= (1.f + __expf(-fabsf(p)));
                    unsigned mw = (r == 0) ? m0 : ((r == 1) ? m1 : m2);
                    if (mw & (1u << lane)) ctgt += p;
                }
            }
            a4 += clin + __logf(cprod);
            a5 += ctgt;
            if (lane == 0) {
                float ov = obj[b * GGV + cell_n];
                a1 += ov;
                a2 += fsp(ov);
                a3 += 1.f;
            }
            if (lane < 4) {
                float rt = (lane == 0) ? rv0 : (lane == 1) ? rv1 : (lane == 2) ? rv2 : rv3;
                float d = reg[(b * 4 + lane) * GGV + cell_n] - rt;
                a6 += d * d;
            }
        }
    }

    // ---- block reduction: warp shuffle -> smem -> warp0 ----
    __shared__ float sm[NTHR / 32][7];
    __shared__ float red[NBLK];
    __shared__ int   s_last;
    {
        float v[7] = {a0, a1, a2, a3, a4, a5, a6};
#pragma unroll
        for (int k = 0; k < 7; ++k) {
            float t = v[k];
#pragma unroll
            for (int o = 16; o; o >>= 1) t += __shfl_down_sync(FULL, t, o);
            if (lane == 0) sm[wid][k] = t;
        }
    }
    __syncthreads();
    if (wid == 0) {
#pragma unroll
        for (int k = 0; k < 7; ++k) {
            float t = (lane < NTHR / 32) ? sm[lane][k] : 0.f;
#pragma unroll
            for (int o = 4; o; o >>= 1) t += __shfl_down_sync(FULL, t, o);
            if (lane == 0) g_part[blockIdx.x][k] = t;
        }
    }
    // ---- last-block finalize (graph-replay-safe: counter self-resets) ----
    if (threadIdx.x == 0) {
        __threadfence();
        int t = atomicAdd(&g_sync, 1);
        s_last = (t == NBLK - 1) ? 1 : 0;
    }
    __syncthreads();
    if (s_last) {
        int t = threadIdx.x;
        float tot[7];
#pragma unroll
        for (int k = 0; k < 7; ++k) {
            if (t < NBLK) red[t] = g_part[t][k];
            __syncthreads();
            for (int s = NBLK / 2; s > 0; s >>= 1) {
                if (t < s) red[t] += red[t + s];
                __syncthreads();
            }
            tot[k] = red[0];
            __syncthreads();
        }
        if (t == 0) {
            const double LN2 = 0.6931471805599453;
            double M     = (double)tot[3];
            double obj_l = (double)tot[0] - (double)tot[1];
            double noobj = 0.5 * ((double)tot[0] - (double)tot[2] + M * LN2);
            double coord = 5.0 * (double)tot[6];
            double cls_l = (double)CV * LN2 * ((double)(BV * GGV) - M)
                         + (double)tot[4] - (double)tot[5];
            double total = obj_l + noobj + coord + cls_l;
            out[0] = (float)(total / (double)BV);
            out[1] = (float)(obj_l / (double)BV);
            out[2] = (float)(noobj / (double)BV);
            out[3] = (float)(coord / (double)BV);
            out[4] = (float)(cls_l / (double)BV);
            g_sync = 0;   // reset for next graph replay
        }
    }
}

// ---------------- launch ----------------
extern "C" void kernel_launch(void* const* d_in, const int* in_sizes, int n_in,
                              void* d_out, int out_size) {
    // Identify inputs by element count (all distinct) to be robust to ordering.
    const float* cls = nullptr;   // 32*80*128*128 = 41943040
    const float* reg = nullptr;   // 32*4*128*128  = 2097152
    const float* obj = nullptr;   // 32*1*128*128  = 524288
    const int*   tcl = nullptr;   // 32*32         = 1024
    const float* tbx = nullptr;   // 32*32*4       = 4096
    for (int i = 0; i < n_in; ++i) {
        switch (in_sizes[i]) {
            case 41943040: cls = (const float*)d_in[i]; break;
            case 2097152:  reg = (const float*)d_in[i]; break;
            case 524288:   obj = (const float*)d_in[i]; break;
            case 1024:     tcl = (const int*)d_in[i];   break;
            case 4096:     tbx = (const float*)d_in[i]; break;
            default: break;
        }
    }
    k_fused<<<NBLK, NTHR>>>(cls, reg, obj, tcl, tbx, (float*)d_out);
}

// round 4
// speedup vs baseline: 10.2296x; 1.3035x over previous
#include <cuda_runtime.h>
#include <cstddef>

// Problem constants
#define BV 32
#define CV 80
#define GV 128
#define GGV (GV * GV)     // 16384
#define NV 32
#define NBLK 128
#define NTHR 256

// ---------------- scratch (device globals; no allocations) ----------------
__device__ float g_part[NBLK][8];   // 7 used, pad to 8 for alignment
__device__ int   g_sync = 0;        // reset to 0 by last block each run (graph-replay safe)

// ---------------- helpers ----------------
__device__ __forceinline__ float fsp(float x) {
    // softplus = max(x,0) + log(1 + exp(-|x|))  (matches jax.nn.softplus)
    return fmaxf(x, 0.0f) + __logf(1.0f + __expf(-fabsf(x)));
}

// ---------------- single fused kernel ----------------
__global__ void __launch_bounds__(NTHR) k_fused(const float* __restrict__ cls,
                                                const float* __restrict__ reg,
                                                const float* __restrict__ obj,
                                                const int*   __restrict__ tcl,
                                                const float* __restrict__ tbx,
                                                float* __restrict__ out) {
    float a0 = 0.f; // sum softplus(obj) over all cells
    float a1 = 0.f; // sum obj at masked cells
    float a2 = 0.f; // sum softplus(obj) at masked cells
    float a3 = 0.f; // masked unique-cell count
    float a4 = 0.f; // sum softplus(cls) over masked cells x C
    float a5 = 0.f; // sum cls at target (b,c,cell) entries
    float a6 = 0.f; // sum squared reg diffs at masked cells

    const int tid  = blockIdx.x * NTHR + threadIdx.x;
    const int lane = threadIdx.x & 31;
    const int wid  = threadIdx.x >> 5;
    const int gw   = tid >> 5;           // global warp id: 0..1023
    const unsigned FULL = 0xffffffffu;

    // ---- warp-parallel target dedup FIRST (scattered loads overlap dense pass) ----
    {
        const int b = gw >> 5;      // batch
        const int n = gw & 31;      // target index owned by this warp
        // lane L loads target L of batch b (coalesced: 512B contiguous)
        float4 tb = ((const float4*)tbx)[b * NV + lane];
        int    tc = tcl[b * NV + lane];
        float fx = tb.x * (float)GV, fy = tb.y * (float)GV;
        int gx = (int)floorf(fx);
        int gy = (int)floorf(fy);
        bool valid = (gx >= 0) && (gx < GV) && (gy >= 0) && (gy < GV);
        gx = min(max(gx, 0), GV - 1);
        gy = min(max(gy, 0), GV - 1);
        int cell = gy * GV + gx;
        float one = valid ? 1.f : 0.f;
        // reg_vals (zeroed when invalid — reference multiplies by `one`)
        float r0 = (fx - (float)gx) * one;
        float r1 = (fy - (float)gy) * one;
        float r2 = sqrtf(tb.z) * one;
        float r3 = sqrtf(tb.w) * one;

        int cell_n  = __shfl_sync(FULL, cell, n);
        int valid_n = __shfl_sync(FULL, (int)valid, n);
        unsigned matchAny = __ballot_sync(FULL, cell == cell_n);            // any validity (.set last-wins)
        unsigned matchVal = __ballot_sync(FULL, valid && (cell == cell_n)); // valid writers (mask/cls)

        // representative: target n is valid and is the FIRST valid lane with this cell
        bool rep = valid_n && ((matchVal & ((1u << n) - 1u)) == 0u);

        // last writer of reg_target at this cell (any validity; .set semantics)
        int k_last = 31 - __clz((int)matchAny);   // bit n always set
        float rv0 = __shfl_sync(FULL, r0, k_last);
        float rv1 = __shfl_sync(FULL, r1, k_last);
        float rv2 = __shfl_sync(FULL, r2, k_last);
        float rv3 = __shfl_sync(FULL, r3, k_last);

        // class bitmask for this cell (union over valid matching lanes)
        bool vm = valid && (cell == cell_n);
        unsigned m0 = __reduce_or_sync(FULL, (vm && tc < 32)             ? (1u << (tc & 31)) : 0u);
        unsigned m1 = __reduce_or_sync(FULL, (vm && tc >= 32 && tc < 64) ? (1u << (tc & 31)) : 0u);
        unsigned m2 = __reduce_or_sync(FULL, (vm && tc >= 64)            ? (1u << (tc & 31)) : 0u);

        if (rep) {
            // warp-parallel gather over the 80 classes (3 per lane, issued back-to-back)
            const float* base = cls + (size_t)b * CV * GGV + cell_n;
            float p0 = base[(size_t)lane * GGV];
            float p1 = base[(size_t)(lane + 32) * GGV];
            float p2 = (lane < CV - 64) ? base[(size_t)(lane + 64) * GGV] : 0.f;
            float ov = (lane == 0) ? obj[b * GGV + cell_n] : 0.f;
            float rg = (lane < 4) ? reg[(b * 4 + lane) * GGV + cell_n] : 0.f;

            float clin = fmaxf(p0, 0.f) + fmaxf(p1, 0.f) + fmaxf(p2, 0.f);
            float cprod = (1.f + __expf(-fabsf(p0)))
                        * (1.f + __expf(-fabsf(p1)))
                        * ((lane < CV - 64) ? (1.f + __expf(-fabsf(p2))) : 1.f);
            float ctgt = 0.f;
            if (m0 & (1u << lane)) ctgt += p0;
            if (m1 & (1u << lane)) ctgt += p1;
            if ((lane < CV - 64) && (m2 & (1u << lane))) ctgt += p2;

            a4 += clin + __logf(cprod);
            a5 += ctgt;
            if (lane == 0) {
                a1 += ov;
                a2 += fsp(ov);
                a3 += 1.f;
            }
            if (lane < 4) {
                float rt = (lane == 0) ? rv0 : (lane == 1) ? rv1 : (lane == 2) ? rv2 : rv3;
                float d = rg - rt;
                a6 += d * d;
            }
        }
    }

    // ---- dense softplus sum over obj_pred (float4, 4 iters/thread, streaming) ----
    {
        const float4* o4 = (const float4*)obj;
        float lin = 0.f, prod = 1.f;
#pragma unroll
        for (int r = 0; r < 4; ++r) {
            float4 v = __ldcs(&o4[tid + r * (NBLK * NTHR)]);
            lin += fmaxf(v.x, 0.f) + fmaxf(v.y, 0.f) + fmaxf(v.z, 0.f) + fmaxf(v.w, 0.f);
            prod *= (1.f + __expf(-fabsf(v.x)));   // each factor in (1,2]; <=16 factors, fp32-safe
            prod *= (1.f + __expf(-fabsf(v.y)));
            prod *= (1.f + __expf(-fabsf(v.z)));
            prod *= (1.f + __expf(-fabsf(v.w)));
        }
        a0 = lin + __logf(prod);
    }

    // ---- block reduction: warp shuffle -> smem -> warp0 ----
    __shared__ float sm[NTHR / 32][8];
    __shared__ float totsm[8];
    __shared__ int   s_last;
    {
        float v[7] = {a0, a1, a2, a3, a4, a5, a6};
#pragma unroll
        for (int k = 0; k < 7; ++k) {
            float t = v[k];
#pragma unroll
            for (int o = 16; o; o >>= 1) t += __shfl_down_sync(FULL, t, o);
            if (lane == 0) sm[wid][k] = t;
        }
    }
    __syncthreads();
    if (wid == 0) {
#pragma unroll
        for (int k = 0; k < 7; ++k) {
            float t = (lane < NTHR / 32) ? sm[lane][k] : 0.f;
#pragma unroll
            for (int o = 4; o; o >>= 1) t += __shfl_down_sync(FULL, t, o);
            if (lane == 0) g_part[blockIdx.x][k] = t;
        }
    }
    // ---- last-block finalize (graph-replay-safe: counter self-resets) ----
    if (threadIdx.x == 0) {
        __threadfence();
        int t = atomicAdd(&g_sync, 1);
        s_last = (t == NBLK - 1) ? 1 : 0;
    }
    __syncthreads();
    if (s_last) {
        // warp k (k<7) reduces component k over all 128 block partials:
        // lane sums 4 strided partials, then 5-step shuffle tree. Fixed order
        // -> deterministic. One __syncthreads total (vs ~50 before).
        if (wid < 7) {
            float t = g_part[lane][wid]
                    + g_part[lane + 32][wid]
                    + g_part[lane + 64][wid]
                    + g_part[lane + 96][wid];
#pragma unroll
            for (int o = 16; o; o >>= 1) t += __shfl_down_sync(FULL, t, o);
            if (lane == 0) totsm[wid] = t;
        }
        __syncthreads();
        if (threadIdx.x == 0) {
            const double LN2 = 0.6931471805599453;
            double t0 = totsm[0], t1 = totsm[1], t2 = totsm[2], t3 = totsm[3];
            double t4 = totsm[4], t5 = totsm[5], t6 = totsm[6];
            double M     = t3;
            double obj_l = t0 - t1;
            double noobj = 0.5 * (t0 - t2 + M * LN2);
            double coord = 5.0 * t6;
            double cls_l = (double)CV * LN2 * ((double)(BV * GGV) - M) + t4 - t5;
            double total = obj_l + noobj + coord + cls_l;
            out[0] = (float)(total / (double)BV);
            out[1] = (float)(obj_l / (double)BV);
            out[2] = (float)(noobj / (double)BV);
            out[3] = (float)(coord / (double)BV);
            out[4] = (float)(cls_l / (double)BV);
            g_sync = 0;   // reset for next graph replay
        }
    }
}

// ---------------- launch ----------------
extern "C" void kernel_launch(void* const* d_in, const int* in_sizes, int n_in,
                              void* d_out, int out_size) {
    // Identify inputs by element count (all distinct) to be robust to ordering.
    const float* cls = nullptr;   // 32*80*128*128 = 41943040
    const float* reg = nullptr;   // 32*4*128*128  = 2097152
    const float* obj = nullptr;   // 32*1*128*128  = 524288
    const int*   tcl = nullptr;   // 32*32         = 1024
    const float* tbx = nullptr;   // 32*32*4       = 4096
    for (int i = 0; i < n_in; ++i) {
        switch (in_sizes[i]) {
            case 41943040: cls = (const float*)d_in[i]; break;
            case 2097152:  reg = (const float*)d_in[i]; break;
            case 524288:   obj = (const float*)d_in[i]; break;
            case 1024:     tcl = (const int*)d_in[i];   break;
            case 4096:     tbx = (const float*)d_in[i]; break;
            default: break;
        }
    }
    k_fused<<<NBLK, NTHR>>>(cls, reg, obj, tcl, tbx, (float*)d_out);
}